// round 7
// baseline (speedup 1.0000x reference)
#include <cuda_runtime.h>

#define Nn 128
#define Ff 16
#define FP 32
#define NM1 127u
#define CHUNKS 16

__global__ void __launch_bounds__(256) gat_fused(
    const float* __restrict__ x,
    const float* __restrict__ w,
    const float* __restrict__ a,
    float*       __restrict__ out,
    int NR, int epb)
{
    __shared__ float v1[Ff], v2[Ff], s1[Nn], s2[Nn];
    const int tid = threadIdx.x;
    const int b   = blockIdx.y;

    // --- prefetch x into registers (warps 0-3), overlapping with v-compute ---
    float xr[Ff];
    if (tid < Nn) {
        const float* xb = x + (size_t)b * Ff * Nn + tid;
        #pragma unroll
        for (int f = 0; f < Ff; ++f)
            xr[f] = xb[f * Nn];            // LDGs issued before the barrier
    }

    // --- warp 4 computes v1/v2 concurrently with the x prefetch ---
    if (tid >= 128 && tid < 160) {
        const int t = tid - 128;
        const int f = t & (Ff - 1);
        const float* av = a + (t < Ff ? 0 : FP);
        float acc = 0.f;
        #pragma unroll
        for (int g = 0; g < FP; ++g)
            acc += w[g * Ff + f] * av[g];
        if (t < Ff) v1[f] = acc; else v2[f] = acc;
    }
    __syncthreads();

    // --- s1[n] = x[b,:,n].v1 ; s2[n] = x[b,:,n].v2 (x already in regs) ---
    if (tid < Nn) {
        float acc1 = 0.f, acc2 = 0.f;
        #pragma unroll
        for (int f = 0; f < Ff; ++f) {
            acc1 += xr[f] * v1[f];
            acc2 += xr[f] * v2[f];
        }
        s1[tid] = acc1;
        s2[tid] = acc2;
    }
    __syncthreads();

    // --- gather: edge e -> r = e/127, k = e%127, s = k + (k>=r) ---
    // stride-256 so lanes access consecutive s2 entries (conflict-free LDS)
    const int e0 = blockIdx.x * epb;
    const int e1 = min(e0 + epb, NR);
    float* ob = out + (size_t)b * NR;

    #pragma unroll 4
    for (int e = e0 + tid; e < e1; e += 256) {
        const unsigned ee = (unsigned)e;
        const unsigned r  = ee / NM1;
        const unsigned k  = ee - r * NM1;
        const unsigned s  = k + (k >= r);
        ob[e] = s1[r] + s2[s];
    }
}

extern "C" void kernel_launch(void* const* d_in, const int* in_sizes, int n_in,
                              void* d_out, int out_size) {
    const float* x = (const float*)d_in[0];
    const float* w = (const float*)d_in[1];
    const float* a = (const float*)d_in[2];
    float*     out = (float*)d_out;

    const int B  = in_sizes[0] / (Ff * Nn);   // x is (B, F, N)
    const int NR = in_sizes[3];               // number of edges (= N*(N-1))

    const int epb = (NR + CHUNKS - 1) / CHUNKS;
    dim3 grid(CHUNKS, B);
    gat_fused<<<grid, 256>>>(x, w, a, out, NR, epb);
}

// round 8
// speedup vs baseline: 1.1255x; 1.1255x over previous
#include <cuda_runtime.h>

#define Nn 128
#define Ff 16
#define FP 32
#define NM1 127u
#define CHUNKS 8

__global__ void __launch_bounds__(256) gat_fused(
    const float* __restrict__ x,
    const float* __restrict__ w,
    const float* __restrict__ a,
    float*       __restrict__ out,
    int NR, int epb)
{
    __shared__ float v1[Ff], v2[Ff], s1[Nn], s2[Nn];
    const int tid = threadIdx.x;
    const int b   = blockIdx.y;

    // --- threads 0..127: x prefetch LDGs issued first (latency overlapped) ---
    float xr[Ff];
    if (tid < Nn) {
        const float* xb = x + (size_t)b * Ff * Nn + tid;
        #pragma unroll
        for (int f = 0; f < Ff; ++f)
            xr[f] = xb[f * Nn];
    }

    // --- warp 4 computes v1/v2 = w^T a1 / w^T a2 concurrently ---
    if (tid >= 128 && tid < 160) {
        const int t = tid - 128;
        const int f = t & (Ff - 1);
        const float* av = a + (t < Ff ? 0 : FP);
        float acc = 0.f;
        #pragma unroll
        for (int g = 0; g < FP; ++g)
            acc += w[g * Ff + f] * av[g];
        if (t < Ff) v1[f] = acc; else v2[f] = acc;
    }
    __syncthreads();

    // --- s1[n] = x[b,:,n].v1 ; s2[n] = x[b,:,n].v2 (x already in regs) ---
    if (tid < Nn) {
        float acc1 = 0.f, acc2 = 0.f;
        #pragma unroll
        for (int f = 0; f < Ff; ++f) {
            acc1 += xr[f] * v1[f];
            acc2 += xr[f] * v2[f];
        }
        s1[tid] = acc1;
        s2[tid] = acc2;
    }
    __syncthreads();

    // --- gather-add, float4 over flat edge index ---
    // edge e -> r = e/127, k = e%127, s = k + (k>=r)
    const int e0 = blockIdx.x * epb;
    const int e1 = min(e0 + epb, NR);
    float* ob = out + (size_t)b * NR;

    for (int e = e0 + tid * 4; e + 3 < e1; e += 256 * 4) {
        float4 o;
        {
            unsigned ee = e + 0, r = ee / NM1, k = ee - r * NM1, s = k + (k >= r);
            o.x = s1[r] + s2[s];
        }
        {
            unsigned ee = e + 1, r = ee / NM1, k = ee - r * NM1, s = k + (k >= r);
            o.y = s1[r] + s2[s];
        }
        {
            unsigned ee = e + 2, r = ee / NM1, k = ee - r * NM1, s = k + (k >= r);
            o.z = s1[r] + s2[s];
        }
        {
            unsigned ee = e + 3, r = ee / NM1, k = ee - r * NM1, s = k + (k >= r);
            o.w = s1[r] + s2[s];
        }
        *reinterpret_cast<float4*>(ob + e) = o;
    }

    // tail (epb padded to multiple of 4, so only the final ragged chunk)
    const int tail_start = e0 + ((e1 - e0) & ~3);
    for (int e = tail_start + tid; e < e1; e += 256) {
        unsigned ee = e, r = ee / NM1, k = ee - r * NM1, s = k + (k >= r);
        ob[e] = s1[r] + s2[s];
    }
}

extern "C" void kernel_launch(void* const* d_in, const int* in_sizes, int n_in,
                              void* d_out, int out_size) {
    const float* x = (const float*)d_in[0];
    const float* w = (const float*)d_in[1];
    const float* a = (const float*)d_in[2];
    float*     out = (float*)d_out;

    const int B  = in_sizes[0] / (Ff * Nn);   // x is (B, F, N)
    const int NR = in_sizes[3];               // N*(N-1) = 16256

    int epb = (NR + CHUNKS - 1) / CHUNKS;
    epb = (epb + 3) & ~3;                     // float4 alignment per chunk
    dim3 grid(CHUNKS, B);
    gat_fused<<<grid, 256>>>(x, w, a, out, NR, epb);
}